// round 6
// baseline (speedup 1.0000x reference)
#include <cuda_runtime.h>
#include <cstdint>

// ---------------------------------------------------------------------------
// QuantizerEncoder: 1-pass tf32 HMMA scores + top-2 gap, then exact fp32
// refinement of ambiguous (small-gap) entries.
//
//   score[code][px] = sum_d Mmat[code][d] * x[d][px]
//   Mmat[k][d] = sum_c wq[c][d]*keys[k][c];  keys[k][c] = sum_d cb[k][d]*wk[c][d]
//   out[n,h,w,m] = argmax_code score  (written as float)
// ---------------------------------------------------------------------------

typedef unsigned long long ULL;

__device__ float g_keys[4 * 256 * 128];   // [m][k][c]
__device__ float g_A[262144];             // hi tf32, frag layout [m][half][w][ks][lane*4+fi]
__device__ float g_M[4 * 256 * 128];      // plain fp32 Mmat [m][k][d] (refine path)
__device__ float g_gap[262144];           // per (pixel, m) top-2 gap

#define GAP_TH 0.08f

static __device__ __forceinline__ uint32_t f2tf32(float v) {
    uint32_t u;
    asm("cvt.rna.tf32.f32 %0, %1;" : "=r"(u) : "f"(v));
    return u;
}

static __device__ __forceinline__ void mma8(float* d, float4 a, float2 b) {
    asm volatile(
        "mma.sync.aligned.m16n8k8.row.col.f32.tf32.tf32.f32 "
        "{%0,%1,%2,%3}, {%4,%5,%6,%7}, {%8,%9}, {%0,%1,%2,%3};"
        : "+f"(d[0]), "+f"(d[1]), "+f"(d[2]), "+f"(d[3])
        : "r"(__float_as_uint(a.x)), "r"(__float_as_uint(a.y)),
          "r"(__float_as_uint(a.z)), "r"(__float_as_uint(a.w)),
          "r"(__float_as_uint(b.x)), "r"(__float_as_uint(b.y)));
}

// monotone float->uint map (order-preserving) and inverse
static __device__ __forceinline__ unsigned mono(float f) {
    unsigned u = __float_as_uint(f);
    return (u & 0x80000000u) ? ~u : (u | 0x80000000u);
}
static __device__ __forceinline__ float imono(unsigned u) {
    return (u & 0x80000000u) ? __uint_as_float(u & 0x7fffffffu)
                             : __uint_as_float(~u);
}

// ---------------- setup 1: keys[m][k][c] = sum_d cb[m][k][d]*wk[m][c][d] ----
__global__ __launch_bounds__(256, 1)
void keys_kernel(const float* __restrict__ cb, const float* __restrict__ wk) {
    extern __shared__ float sm[];
    float* swkT = sm;            // [128 d][129]
    float* scb = sm + 129 * 128; // [8 k][128 d]
    const int m = blockIdx.y, kch = blockIdx.x, t = threadIdx.x;

    const float4* wk4 = (const float4*)(wk + (size_t)m * 16384);
#pragma unroll
    for (int i = 0; i < 16; i++) {
        int j = i * 256 + t, c = j >> 5, d4 = j & 31;
        float4 v = __ldg(wk4 + j);
        swkT[(4 * d4 + 0) * 129 + c] = v.x;
        swkT[(4 * d4 + 1) * 129 + c] = v.y;
        swkT[(4 * d4 + 2) * 129 + c] = v.z;
        swkT[(4 * d4 + 3) * 129 + c] = v.w;
    }
    ((float4*)scb)[t] = __ldg((const float4*)(cb + ((size_t)m * 256 + kch * 8) * 128) + t);
    __syncthreads();
#pragma unroll
    for (int i = 0; i < 4; i++) {
        int o = i * 256 + t, kl = o >> 7, c = o & 127;
        float s = 0.f;
#pragma unroll 8
        for (int d = 0; d < 128; d++) s += scb[kl * 128 + d] * swkT[d * 129 + c];
        g_keys[((size_t)m * 256 + kch * 8 + kl) * 128 + c] = s;
    }
}

// ---------------- setup 2: Mmat -> tf32-hi frag layout + plain fp32 ---------
__global__ __launch_bounds__(256, 1)
void mmat_kernel(const float* __restrict__ wq) {
    extern __shared__ float sm[];
    float* swq = sm;             // [128 c][128 d]
    float* skeys = sm + 16384;   // [8 k][128 c]
    const int m = blockIdx.y, kch = blockIdx.x, t = threadIdx.x;

    const float4* wq4 = (const float4*)(wq + (size_t)m * 16384);
#pragma unroll
    for (int i = 0; i < 16; i++) ((float4*)swq)[i * 256 + t] = __ldg(wq4 + i * 256 + t);
    ((float4*)skeys)[t] =
        ((const float4*)(g_keys + ((size_t)m * 256 + kch * 8) * 128))[t];
    __syncthreads();
#pragma unroll
    for (int i = 0; i < 4; i++) {
        int o = i * 256 + t, kl = o >> 7, d = o & 127;
        float val = 0.f;
#pragma unroll 8
        for (int c = 0; c < 128; c++) val += swq[c * 128 + d] * skeys[kl * 128 + c];
        int k = kch * 8 + kl;
        g_M[((size_t)m * 256 + k) * 128 + d] = val;

        // hi tf32 in m16n8k8 A-frag layout
        uint32_t hib = f2tf32(val);
        int half_ = k >> 7, w = (k & 127) >> 4, r = k & 15;
        int ks = d >> 3, dc = d & 7;
        int ln, fi;
        if (r < 8) { ln = r * 4 + (dc & 3); fi = (dc >= 4) ? 2 : 0; }
        else       { ln = (r - 8) * 4 + (dc & 3); fi = (dc >= 4) ? 3 : 1; }
        size_t base = (size_t)(((m * 2 + half_) * 8 + w) * 16 + ks) * 128 + ln * 4 + fi;
        g_A[base] = __uint_as_float(hib);
    }
}

// ---------------- stage 1: 1-pass tf32 score + top-2 + gap ------------------
// CTA: 256 threads, 128 px, one m. grid = (512, 4). 2 CTAs/SM.
// smem: B hi frag 16384 f (64KB) + gkeys ULL[16*128] (16KB) + gsecs u32[16*128] (8KB)
__global__ __launch_bounds__(256, 2)
void score_kernel(const float* __restrict__ latent, float* __restrict__ out) {
    extern __shared__ float sb[];
    ULL* gkeys = (ULL*)(sb + 16384);
    unsigned* gsecs = (unsigned*)(sb + 16384 + 4096);

    const int t = threadIdx.x, lane = t & 31, wid = t >> 5;
    const int m = blockIdx.y;
    const int n = blockIdx.x >> 5;
    const int p0 = (blockIdx.x & 31) << 7;

    // ---- convert latent [128 d][128 px] -> tf32 hi, frag-linear smem ----
    const float* xb = latent + ((size_t)(n * 512 + m * 128)) * 4096 + p0;
#pragma unroll
    for (int i = 0; i < 16; i++) {
        int idx = i * 256 + t;
        int d = idx >> 5, p4 = idx & 31;
        float4 v = __ldg((const float4*)(xb + (size_t)d * 4096) + p4);
        float e[4] = {v.x, v.y, v.z, v.w};
        int sp = d >> 4, w1 = (d >> 3) & 1;
        int ee = w1 * 2 + ((d & 4) ? 1 : 0);
#pragma unroll
        for (int q = 0; q < 4; q++) {
            int c = (t + q) & 3;
            int px = p4 * 4 + c;
            int j = px >> 3;
            int ln = ((px & 7) << 2) | (d & 3);
            int off = ((j * 8 + sp) * 32 + ln) * 4 + ee;
            sb[off] = __uint_as_float(f2tf32(e[c]));
        }
    }
    __syncthreads();

    for (int half_ = 0; half_ < 2; half_++) {
        float acc[16][4];
#pragma unroll
        for (int j = 0; j < 16; j++)
#pragma unroll
            for (int c = 0; c < 4; c++) acc[j][c] = 0.f;

        const float4* pA = ((const float4*)g_A) +
                           (size_t)((m * 2 + half_) * 8 + wid) * 512;

#pragma unroll 4
        for (int ks = 0; ks < 16; ks++) {
            float4 ah = __ldg(pA + ks * 32 + lane);
            int sp = ks >> 1, w1 = ks & 1;
#pragma unroll
            for (int j = 0; j < 16; j++) {
                int f = ((j * 8 + sp) * 32 + lane) * 4 + w1 * 2;
                float2 bh = *(const float2*)(sb + f);
                mma8(acc[j], ah, bh);
            }
        }

        // ---- top-2 over this warp's 16 codes, per pixel ----
        int r0 = half_ * 128 + wid * 16 + (lane >> 2);
#pragma unroll
        for (int j = 0; j < 16; j++) {
#pragma unroll
            for (int cc = 0; cc < 2; cc++) {
                unsigned u0 = mono(acc[j][cc]);       // code r0
                unsigned u1 = mono(acc[j][2 + cc]);   // code r0+8
                ULL k0 = ((ULL)u0 << 32) | (unsigned)(255 - r0);
                ULL k1 = ((ULL)u1 << 32) | (unsigned)(255 - (r0 + 8));
                ULL key = (k0 > k1) ? k0 : k1;
                unsigned us = (u0 < u1) ? u0 : u1;
#pragma unroll
                for (int o = 4; o <= 16; o <<= 1) {
                    ULL ok = __shfl_xor_sync(0xffffffffu, key, o);
                    unsigned os = __shfl_xor_sync(0xffffffffu, us, o);
                    unsigned loser_b = (unsigned)(((key < ok) ? key : ok) >> 32);
                    unsigned win_s = (key > ok) ? us : os;
                    us = (loser_b > win_s) ? loser_b : win_s;
                    key = (key > ok) ? key : ok;
                }
                if (lane < 4) {
                    int px = j * 8 + lane * 2 + cc;
                    gkeys[(half_ * 8 + wid) * 128 + px] = key;
                    gsecs[(half_ * 8 + wid) * 128 + px] = us;
                }
            }
        }
    }
    __syncthreads();

    if (t < 128) {
        int px = t;
        ULL k1 = gkeys[px];
        int g1 = 0;
        unsigned u2 = 0;
#pragma unroll
        for (int g = 1; g < 16; g++) {
            ULL kb = gkeys[g * 128 + px];
            if (kb > k1) {
                unsigned pb = (unsigned)(k1 >> 32);
                if (pb > u2) u2 = pb;
                k1 = kb; g1 = g;
            } else {
                unsigned pb = (unsigned)(kb >> 32);
                if (pb > u2) u2 = pb;
            }
        }
        unsigned sw = gsecs[g1 * 128 + px];
        if (sw > u2) u2 = sw;
        float f1 = imono((unsigned)(k1 >> 32));
        float f2 = imono(u2);
        int code = 255 - (int)(k1 & 0xFF);
        int e = (n * 4096 + p0 + px) * 4 + m;
        out[e] = (float)code;
        g_gap[e] = f1 - f2;
    }
}

// ---------------- stage 2: exact fp32 refinement of small-gap entries -------
// grid = 1024 blocks x 256 threads; one thread per (pixel, m) entry.
__global__ __launch_bounds__(256, 4)
void refine_kernel(const float* __restrict__ latent, float* __restrict__ out) {
    const int t = threadIdx.x, lane = t & 31;
    const int e = blockIdx.x * 256 + t;   // 0..262143
    const int pix = e >> 2, m = e & 3;

    bool flag = g_gap[e] < GAP_TH;
    unsigned mask = __ballot_sync(0xffffffffu, flag);

    while (mask) {
        int src = __ffs(mask) - 1;
        mask &= mask - 1;
        int epix = __shfl_sync(0xffffffffu, pix, src);
        int em = __shfl_sync(0xffffffffu, m, src);

        int nn = epix >> 12, p = epix & 4095;
        const float* xb = latent + ((size_t)(nn * 512 + em * 128)) * 4096 + p;
        float xr[4];
#pragma unroll
        for (int q = 0; q < 4; q++)
            xr[q] = __ldg(xb + (size_t)(4 * lane + q) * 4096);

        const float4* M4 = (const float4*)(g_M + (size_t)em * 32768);
        float acc[8];
#pragma unroll
        for (int c = 0; c < 8; c++) acc[c] = 0.f;

        for (int d4 = 0; d4 < 32; d4++) {
            float x0 = __shfl_sync(0xffffffffu, xr[0], d4);
            float x1 = __shfl_sync(0xffffffffu, xr[1], d4);
            float x2 = __shfl_sync(0xffffffffu, xr[2], d4);
            float x3 = __shfl_sync(0xffffffffu, xr[3], d4);
#pragma unroll
            for (int c = 0; c < 8; c++) {
                float4 mm = __ldg(M4 + (size_t)(lane * 8 + c) * 32 + d4);
                acc[c] += mm.x * x0 + mm.y * x1 + mm.z * x2 + mm.w * x3;
            }
        }

        ULL key = 0;
#pragma unroll
        for (int c = 0; c < 8; c++) {
            int code = lane * 8 + c;
            ULL k = ((ULL)mono(acc[c]) << 32) | (unsigned)(255 - code);
            if (k > key) key = k;
        }
#pragma unroll
        for (int o = 1; o < 32; o <<= 1) {
            ULL ok = __shfl_xor_sync(0xffffffffu, key, o);
            if (ok > key) key = ok;
        }
        if (lane == src) out[epix * 4 + em] = (float)(255 - (int)(key & 0xFF));
    }
}

extern "C" void kernel_launch(void* const* d_in, const int* in_sizes, int n_in,
                              void* d_out, int out_size) {
    const float* latent = (const float*)d_in[0];
    const float* cb     = (const float*)d_in[1];
    const float* wq     = (const float*)d_in[2];
    const float* wk     = (const float*)d_in[3];

    cudaFuncSetAttribute(keys_kernel, cudaFuncAttributeMaxDynamicSharedMemorySize, 70144);
    cudaFuncSetAttribute(mmat_kernel, cudaFuncAttributeMaxDynamicSharedMemorySize, 69632);
    cudaFuncSetAttribute(score_kernel, cudaFuncAttributeMaxDynamicSharedMemorySize, 90112);

    keys_kernel<<<dim3(32, 4), 256, 70144>>>(cb, wk);
    mmat_kernel<<<dim3(32, 4), 256, 69632>>>(wq);
    score_kernel<<<dim3(512, 4), 256, 90112>>>(latent, (float*)d_out);
    refine_kernel<<<1024, 256>>>(latent, (float*)d_out);
}

// round 7
// speedup vs baseline: 2.9745x; 2.9745x over previous
#include <cuda_runtime.h>
#include <cstdint>

// ---------------------------------------------------------------------------
// QuantizerEncoder: 1-pass tf32 HMMA + top-2 gap; flagged entries compacted
// and exactly recomputed in fp32 (batched, coalesced).
//
//   score[code][px] = sum_d Mmat[code][d] * x[d][px]
//   out[n,h,w,m] = argmax_code score  (float-coded index)
// ---------------------------------------------------------------------------

typedef unsigned long long ULL;

__device__ float g_keys[4 * 256 * 128];   // [m][k][c]
__device__ float g_A[262144];             // tf32-hi, m16n8k8 A-frag layout
__device__ float g_MT[4 * 128 * 256];     // fp32 M^T [m][d][k] (refine)
__device__ int   g_cnt[4];                // flagged counts per m
__device__ int   g_list[4 * 65536];       // flagged pixel lists per m

#define GAP_TH 0.08f

static __device__ __forceinline__ uint32_t f2tf32(float v) {
    uint32_t u;
    asm("cvt.rna.tf32.f32 %0, %1;" : "=r"(u) : "f"(v));
    return u;
}

static __device__ __forceinline__ void mma8(float* d, float4 a, float2 b) {
    asm volatile(
        "mma.sync.aligned.m16n8k8.row.col.f32.tf32.tf32.f32 "
        "{%0,%1,%2,%3}, {%4,%5,%6,%7}, {%8,%9}, {%0,%1,%2,%3};"
        : "+f"(d[0]), "+f"(d[1]), "+f"(d[2]), "+f"(d[3])
        : "r"(__float_as_uint(a.x)), "r"(__float_as_uint(a.y)),
          "r"(__float_as_uint(a.z)), "r"(__float_as_uint(a.w)),
          "r"(__float_as_uint(b.x)), "r"(__float_as_uint(b.y)));
}

static __device__ __forceinline__ unsigned mono(float f) {
    unsigned u = __float_as_uint(f);
    return (u & 0x80000000u) ? ~u : (u | 0x80000000u);
}
static __device__ __forceinline__ float imono(unsigned u) {
    return (u & 0x80000000u) ? __uint_as_float(u & 0x7fffffffu)
                             : __uint_as_float(~u);
}

// ---------------- setup 1: keys[m][k][c] = sum_d cb[m][k][d]*wk[m][c][d] ----
__global__ __launch_bounds__(256, 1)
void keys_kernel(const float* __restrict__ cb, const float* __restrict__ wk) {
    extern __shared__ float sm[];
    float* swkT = sm;            // [128 d][129]
    float* scb = sm + 129 * 128; // [8 k][128 d]
    const int m = blockIdx.y, kch = blockIdx.x, t = threadIdx.x;

    if (blockIdx.x == 0 && blockIdx.y == 0 && t < 4) g_cnt[t] = 0;

    const float4* wk4 = (const float4*)(wk + (size_t)m * 16384);
#pragma unroll
    for (int i = 0; i < 16; i++) {
        int j = i * 256 + t, c = j >> 5, d4 = j & 31;
        float4 v = __ldg(wk4 + j);
        swkT[(4 * d4 + 0) * 129 + c] = v.x;
        swkT[(4 * d4 + 1) * 129 + c] = v.y;
        swkT[(4 * d4 + 2) * 129 + c] = v.z;
        swkT[(4 * d4 + 3) * 129 + c] = v.w;
    }
    ((float4*)scb)[t] = __ldg((const float4*)(cb + ((size_t)m * 256 + kch * 8) * 128) + t);
    __syncthreads();
#pragma unroll
    for (int i = 0; i < 4; i++) {
        int o = i * 256 + t, kl = o >> 7, c = o & 127;
        float s = 0.f;
#pragma unroll 8
        for (int d = 0; d < 128; d++) s += scb[kl * 128 + d] * swkT[d * 129 + c];
        g_keys[((size_t)m * 256 + kch * 8 + kl) * 128 + c] = s;
    }
}

// ---------------- setup 2: Mmat -> tf32-hi frag layout + fp32 M^T -----------
__global__ __launch_bounds__(256, 1)
void mmat_kernel(const float* __restrict__ wq) {
    extern __shared__ float sm[];
    float* swq = sm;             // [128 c][128 d]
    float* skeys = sm + 16384;   // [8 k][128 c]
    const int m = blockIdx.y, kch = blockIdx.x, t = threadIdx.x;

    const float4* wq4 = (const float4*)(wq + (size_t)m * 16384);
#pragma unroll
    for (int i = 0; i < 16; i++) ((float4*)swq)[i * 256 + t] = __ldg(wq4 + i * 256 + t);
    ((float4*)skeys)[t] =
        ((const float4*)(g_keys + ((size_t)m * 256 + kch * 8) * 128))[t];
    __syncthreads();
#pragma unroll
    for (int i = 0; i < 4; i++) {
        int o = i * 256 + t, kl = o >> 7, d = o & 127;
        float val = 0.f;
#pragma unroll 8
        for (int c = 0; c < 128; c++) val += swq[c * 128 + d] * skeys[kl * 128 + c];
        int k = kch * 8 + kl;
        g_MT[((size_t)m * 128 + d) * 256 + k] = val;

        uint32_t hib = f2tf32(val);
        int half_ = k >> 7, w = (k & 127) >> 4, r = k & 15;
        int ks = d >> 3, dc = d & 7;
        int ln, fi;
        if (r < 8) { ln = r * 4 + (dc & 3); fi = (dc >= 4) ? 2 : 0; }
        else       { ln = (r - 8) * 4 + (dc & 3); fi = (dc >= 4) ? 3 : 1; }
        size_t base = (size_t)(((m * 2 + half_) * 8 + w) * 16 + ks) * 128 + ln * 4 + fi;
        g_A[base] = __uint_as_float(hib);
    }
}

// ---------------- stage 1: 1-pass tf32 + top-2 + flag compaction ------------
// CTA: 256 threads, 128 px, one m. grid = (512, 4). 2 CTAs/SM.
// smem: xs canonical [128 d][stride 136] tf32 (69632B)
//       gkeys ULL[16][128] @float 17408, gsecs u32[16][128] @float 21504
__global__ __launch_bounds__(256, 2)
void score_kernel(const float* __restrict__ latent, float* __restrict__ out) {
    extern __shared__ float sb[];
    ULL* gkeys = (ULL*)(sb + 17408);
    unsigned* gsecs = (unsigned*)(sb + 21504);

    const int t = threadIdx.x, lane = t & 31, wid = t >> 5;
    const int m = blockIdx.y;
    const int n = blockIdx.x >> 5;
    const int p0 = (blockIdx.x & 31) << 7;

    // ---- conversion: LDG.128 -> tf32 -> STS.128 (conflict-free) ----
    const float* xb = latent + ((size_t)(n * 512 + m * 128)) * 4096 + p0;
#pragma unroll
    for (int i = 0; i < 16; i++) {
        int idx = i * 256 + t;
        int d = idx >> 5, p4 = idx & 31;
        float4 v = __ldg((const float4*)(xb + (size_t)d * 4096) + p4);
        float4 tf;
        tf.x = __uint_as_float(f2tf32(v.x));
        tf.y = __uint_as_float(f2tf32(v.y));
        tf.z = __uint_as_float(f2tf32(v.z));
        tf.w = __uint_as_float(f2tf32(v.w));
        *(float4*)(sb + d * 136 + p4 * 4) = tf;
    }
    __syncthreads();

    for (int half_ = 0; half_ < 2; half_++) {
        float acc[16][4];
#pragma unroll
        for (int j = 0; j < 16; j++)
#pragma unroll
            for (int c = 0; c < 4; c++) acc[j][c] = 0.f;

        const float4* pA = ((const float4*)g_A) +
                           (size_t)((m * 2 + half_) * 8 + wid) * 512;

#pragma unroll 4
        for (int ks = 0; ks < 16; ks++) {
            float4 ah = __ldg(pA + ks * 32 + lane);
            const float* bbase = sb + (ks * 8 + (lane & 3)) * 136 + (lane >> 2);
#pragma unroll
            for (int j = 0; j < 16; j++) {
                float2 b = make_float2(bbase[j * 8], bbase[544 + j * 8]);
                mma8(acc[j], ah, b);
            }
        }

        // ---- top-2 over this warp's 16 codes, per pixel ----
        int r0 = half_ * 128 + wid * 16 + (lane >> 2);
#pragma unroll
        for (int j = 0; j < 16; j++) {
#pragma unroll
            for (int cc = 0; cc < 2; cc++) {
                unsigned u0 = mono(acc[j][cc]);       // code r0
                unsigned u1 = mono(acc[j][2 + cc]);   // code r0+8
                ULL k0 = ((ULL)u0 << 32) | (unsigned)(255 - r0);
                ULL k1 = ((ULL)u1 << 32) | (unsigned)(255 - (r0 + 8));
                ULL key = (k0 > k1) ? k0 : k1;
                unsigned us = (u0 < u1) ? u0 : u1;
#pragma unroll
                for (int o = 4; o <= 16; o <<= 1) {
                    ULL ok = __shfl_xor_sync(0xffffffffu, key, o);
                    unsigned os = __shfl_xor_sync(0xffffffffu, us, o);
                    unsigned loser_b = (unsigned)(((key < ok) ? key : ok) >> 32);
                    unsigned win_s = (key > ok) ? us : os;
                    us = (loser_b > win_s) ? loser_b : win_s;
                    key = (key > ok) ? key : ok;
                }
                if (lane < 4) {
                    int px = j * 8 + lane * 2 + cc;
                    gkeys[(half_ * 8 + wid) * 128 + px] = key;
                    gsecs[(half_ * 8 + wid) * 128 + px] = us;
                }
            }
        }
    }
    __syncthreads();

    if (t < 128) {
        int px = t;
        ULL k1 = gkeys[px];
        int g1 = 0;
        unsigned u2 = 0;
#pragma unroll
        for (int g = 1; g < 16; g++) {
            ULL kb = gkeys[g * 128 + px];
            if (kb > k1) {
                unsigned pb = (unsigned)(k1 >> 32);
                if (pb > u2) u2 = pb;
                k1 = kb; g1 = g;
            } else {
                unsigned pb = (unsigned)(kb >> 32);
                if (pb > u2) u2 = pb;
            }
        }
        unsigned sw = gsecs[g1 * 128 + px];
        if (sw > u2) u2 = sw;
        float f1 = imono((unsigned)(k1 >> 32));
        float f2 = imono(u2);
        int code = 255 - (int)(k1 & 0xFF);
        int pix = n * 4096 + p0 + px;
        out[pix * 4 + m] = (float)code;
        if (f1 - f2 < GAP_TH) {
            int pos = atomicAdd(&g_cnt[m], 1);
            g_list[m * 65536 + pos] = pix;
        }
    }
}

// ---------------- stage 2: batched exact fp32 refine ------------------------
// CTA processes 32 flagged entries of one m at a time; M^T read coalesced.
__global__ __launch_bounds__(256, 2)
void refine_kernel(const float* __restrict__ latent, float* __restrict__ out) {
    __shared__ float xs[128 * 32];     // [d][e]
    __shared__ ULL redk[32 * 64];      // [e][c4]
    __shared__ int spix[32];

    const int t = threadIdx.x;

    for (int m = 0; m < 4; m++) {
        int cnt = g_cnt[m];
        int nb = (cnt + 31) >> 5;
        for (int jb = blockIdx.x; jb < nb; jb += gridDim.x) {
            int ne = cnt - jb * 32;
            if (ne > 32) ne = 32;
            if (t < 32)
                spix[t] = g_list[m * 65536 + jb * 32 + ((t < ne) ? t : 0)];
            __syncthreads();

            // load x for 32 entries: xs[d][e]
            {
                int e = t & 31, d0 = (t >> 5) * 16;
                int pp = spix[e];
                const float* xp = latent +
                    ((size_t)((pp >> 12) * 512 + m * 128 + d0)) * 4096 + (pp & 4095);
#pragma unroll 4
                for (int i = 0; i < 16; i++)
                    xs[(d0 + i) * 32 + e] = __ldg(xp + (size_t)i * 4096);
            }
            __syncthreads();

            // compute: thread = (c4 = t&63 -> codes 4c4..+3, eg = t>>6 -> 8 entries)
            const int c4 = t & 63, eg = t >> 6;
            float acc[4][8];
#pragma unroll
            for (int c = 0; c < 4; c++)
#pragma unroll
                for (int k = 0; k < 8; k++) acc[c][k] = 0.f;

            const float4* MT = (const float4*)(g_MT + (size_t)m * 32768);
#pragma unroll 4
            for (int d = 0; d < 128; d++) {
                float4 mv = __ldg(MT + d * 64 + c4);
                float4 xa = *(const float4*)(xs + d * 32 + eg * 8);
                float4 xc = *(const float4*)(xs + d * 32 + eg * 8 + 4);
                float xv[8] = {xa.x, xa.y, xa.z, xa.w, xc.x, xc.y, xc.z, xc.w};
#pragma unroll
                for (int k = 0; k < 8; k++) {
                    acc[0][k] += mv.x * xv[k];
                    acc[1][k] += mv.y * xv[k];
                    acc[2][k] += mv.z * xv[k];
                    acc[3][k] += mv.w * xv[k];
                }
            }

#pragma unroll
            for (int k = 0; k < 8; k++) {
                ULL key = 0;
#pragma unroll
                for (int c = 0; c < 4; c++) {
                    int code = c4 * 4 + c;
                    ULL kk = ((ULL)mono(acc[c][k]) << 32) | (unsigned)(255 - code);
                    if (kk > key) key = kk;
                }
                redk[(eg * 8 + k) * 64 + c4] = key;
            }
            __syncthreads();

            {
                int e2 = t >> 3, ch = t & 7;
                ULL best = redk[e2 * 64 + ch * 8];
#pragma unroll
                for (int q = 1; q < 8; q++) {
                    ULL o = redk[e2 * 64 + ch * 8 + q];
                    if (o > best) best = o;
                }
#pragma unroll
                for (int o = 1; o < 8; o <<= 1) {
                    ULL ob = __shfl_xor_sync(0xffffffffu, best, o);
                    if (ob > best) best = ob;
                }
                if (ch == 0 && e2 < ne)
                    out[spix[e2] * 4 + m] = (float)(255 - (int)(best & 0xFF));
            }
            __syncthreads();
        }
    }
}

extern "C" void kernel_launch(void* const* d_in, const int* in_sizes, int n_in,
                              void* d_out, int out_size) {
    const float* latent = (const float*)d_in[0];
    const float* cb     = (const float*)d_in[1];
    const float* wq     = (const float*)d_in[2];
    const float* wk     = (const float*)d_in[3];

    cudaFuncSetAttribute(keys_kernel, cudaFuncAttributeMaxDynamicSharedMemorySize, 70144);
    cudaFuncSetAttribute(mmat_kernel, cudaFuncAttributeMaxDynamicSharedMemorySize, 69632);
    cudaFuncSetAttribute(score_kernel, cudaFuncAttributeMaxDynamicSharedMemorySize, 94208);

    keys_kernel<<<dim3(32, 4), 256, 70144>>>(cb, wk);
    mmat_kernel<<<dim3(32, 4), 256, 69632>>>(wq);
    score_kernel<<<dim3(512, 4), 256, 94208>>>(latent, (float*)d_out);
    refine_kernel<<<128, 256>>>(latent, (float*)d_out);
}

// round 8
// speedup vs baseline: 3.6083x; 1.2131x over previous
#include <cuda_runtime.h>
#include <cstdint>

// ---------------------------------------------------------------------------
// QuantizerEncoder: 1-pass tf32 HMMA + top-2 gap; flagged entries compacted
// and exactly recomputed in fp32 (batched, coalesced).
//
//   score[code][px] = sum_d Mmat[code][d] * x[d][px]
//   out[n,h,w,m] = argmax_code score  (float-coded index)
// ---------------------------------------------------------------------------

typedef unsigned long long ULL;

__device__ float g_A[262144];             // tf32-hi, m16n8k8 A-frag layout
__device__ float g_MT[4 * 128 * 256];     // fp32 M^T [m][d][k] (refine)
__device__ int   g_cnt[4];                // flagged counts per m
__device__ int   g_list[4 * 65536];       // flagged pixel lists per m

#define GAP_TH 0.05f

static __device__ __forceinline__ uint32_t f2tf32(float v) {
    uint32_t u;
    asm("cvt.rna.tf32.f32 %0, %1;" : "=r"(u) : "f"(v));
    return u;
}

static __device__ __forceinline__ uint32_t smem_u32(const void* p) {
    uint32_t a;
    asm("{ .reg .u64 t; cvta.to.shared.u64 t, %1; cvt.u32.u64 %0, t; }"
        : "=r"(a) : "l"(p));
    return a;
}

static __device__ __forceinline__ void mma8(float* d, float4 a, float2 b) {
    asm volatile(
        "mma.sync.aligned.m16n8k8.row.col.f32.tf32.tf32.f32 "
        "{%0,%1,%2,%3}, {%4,%5,%6,%7}, {%8,%9}, {%0,%1,%2,%3};"
        : "+f"(d[0]), "+f"(d[1]), "+f"(d[2]), "+f"(d[3])
        : "r"(__float_as_uint(a.x)), "r"(__float_as_uint(a.y)),
          "r"(__float_as_uint(a.z)), "r"(__float_as_uint(a.w)),
          "r"(__float_as_uint(b.x)), "r"(__float_as_uint(b.y)));
}

static __device__ __forceinline__ unsigned mono(float f) {
    unsigned u = __float_as_uint(f);
    return (u & 0x80000000u) ? ~u : (u | 0x80000000u);
}
static __device__ __forceinline__ float imono(unsigned u) {
    return (u & 0x80000000u) ? __uint_as_float(u & 0x7fffffffu)
                             : __uint_as_float(~u);
}

// ---------------- fused setup: keys (smem) -> Mmat -> g_A/g_MT --------------
// grid (32, 4), 256 threads. smem: region0 16512 f (swkT [128][129] then
// swq [128c][128d]), skeys @16512 (1024 f), scb @17536 (1024 f). 74240 B.
__global__ __launch_bounds__(256, 1)
void setup_kernel(const float* __restrict__ cb, const float* __restrict__ wk,
                  const float* __restrict__ wq) {
    extern __shared__ float sm[];
    float* skeys = sm + 16512;   // [8 k][128 c]
    float* scb   = sm + 17536;   // [8 k][128 d]
    const int m = blockIdx.y, kch = blockIdx.x, t = threadIdx.x;

    // phase 1: keys[k][c] = sum_d cb[k][d] * wk[c][d]
    const float4* wk4 = (const float4*)(wk + (size_t)m * 16384);
#pragma unroll
    for (int i = 0; i < 16; i++) {
        int j = i * 256 + t, c = j >> 5, d4 = j & 31;
        float4 v = __ldg(wk4 + j);
        sm[(4 * d4 + 0) * 129 + c] = v.x;
        sm[(4 * d4 + 1) * 129 + c] = v.y;
        sm[(4 * d4 + 2) * 129 + c] = v.z;
        sm[(4 * d4 + 3) * 129 + c] = v.w;
    }
    ((float4*)scb)[t] = __ldg((const float4*)(cb + ((size_t)m * 256 + kch * 8) * 128) + t);
    __syncthreads();
#pragma unroll
    for (int i = 0; i < 4; i++) {
        int o = i * 256 + t, kl = o >> 7, c = o & 127;
        float s = 0.f;
#pragma unroll 8
        for (int d = 0; d < 128; d++) s += scb[kl * 128 + d] * sm[d * 129 + c];
        skeys[kl * 128 + c] = s;
    }
    __syncthreads();

    // phase 2: Mmat[k][d] = sum_c wq[c][d] * keys[k][c]
    const float4* wq4 = (const float4*)(wq + (size_t)m * 16384);
#pragma unroll
    for (int i = 0; i < 16; i++) ((float4*)sm)[i * 256 + t] = __ldg(wq4 + i * 256 + t);
    __syncthreads();
#pragma unroll
    for (int i = 0; i < 4; i++) {
        int o = i * 256 + t, kl = o >> 7, d = o & 127;
        float val = 0.f;
#pragma unroll 8
        for (int c = 0; c < 128; c++) val += sm[c * 128 + d] * skeys[kl * 128 + c];
        int k = kch * 8 + kl;
        g_MT[((size_t)m * 128 + d) * 256 + k] = val;

        uint32_t hib = f2tf32(val);
        int half_ = k >> 7, w = (k & 127) >> 4, r = k & 15;
        int ks = d >> 3, dc = d & 7;
        int ln, fi;
        if (r < 8) { ln = r * 4 + (dc & 3); fi = (dc >= 4) ? 2 : 0; }
        else       { ln = (r - 8) * 4 + (dc & 3); fi = (dc >= 4) ? 3 : 1; }
        size_t base = (size_t)(((m * 2 + half_) * 8 + w) * 16 + ks) * 128 + ln * 4 + fi;
        g_A[base] = __uint_as_float(hib);
    }
    if (blockIdx.x == 0 && blockIdx.y == 0 && t < 4) g_cnt[t] = 0;
}

// ---------------- stage 1: 1-pass tf32 + top-2 + flag compaction ------------
// CTA: 256 threads, 128 px, one m. grid = (512, 4). 2 CTAs/SM.
// smem floats: [0,17408) B tf32 [128 d][136]; [17408,25600) staging raw hi-d;
// gkeys ULL[16][128] @17408 and gsecs u32 @21504 overlap staging (staging is
// dead before they are written). Total 102400 B.
__global__ __launch_bounds__(256, 2)
void score_kernel(const float* __restrict__ latent, float* __restrict__ out) {
    extern __shared__ float sb[];
    float* stage = sb + 17408;
    ULL* gkeys = (ULL*)(sb + 17408);
    unsigned* gsecs = (unsigned*)(sb + 21504);

    const int t = threadIdx.x, lane = t & 31, wid = t >> 5;
    const int m = blockIdx.y;
    const int n = blockIdx.x >> 5;
    const int p0 = (blockIdx.x & 31) << 7;

    const float* xb = latent + ((size_t)(n * 512 + m * 128)) * 4096 + p0;
    const uint32_t stg = smem_u32(stage);

    // kick off async stage of hi-d half (d 64..127) raw fp32
#pragma unroll
    for (int i = 0; i < 8; i++) {
        int idx = i * 256 + t;
        int dh = idx >> 5, p4 = idx & 31;
        const float* src = xb + (size_t)(64 + dh) * 4096 + p4 * 4;
        asm volatile("cp.async.cg.shared.global [%0], [%1], 16;"
                     :: "r"(stg + idx * 16), "l"(src));
    }
    asm volatile("cp.async.commit_group;");

    // direct conversion of lo-d half (d 0..63)
#pragma unroll
    for (int i = 0; i < 8; i++) {
        int idx = i * 256 + t;
        int d = idx >> 5, p4 = idx & 31;
        float4 v = __ldg((const float4*)(xb + (size_t)d * 4096) + p4);
        float4 tf;
        tf.x = __uint_as_float(f2tf32(v.x));
        tf.y = __uint_as_float(f2tf32(v.y));
        tf.z = __uint_as_float(f2tf32(v.z));
        tf.w = __uint_as_float(f2tf32(v.w));
        *(float4*)(sb + d * 136 + p4 * 4) = tf;
    }
    __syncthreads();

    for (int half_ = 0; half_ < 2; half_++) {
        float acc[16][4];
#pragma unroll
        for (int j = 0; j < 16; j++)
#pragma unroll
            for (int c = 0; c < 4; c++) acc[j][c] = 0.f;

        const float4* pA = ((const float4*)g_A) +
                           (size_t)((m * 2 + half_) * 8 + wid) * 512;

        for (int kg = 0; kg < 2; kg++) {
            if (half_ == 0 && kg == 1) {
                // hi-d staging done by now? wait + convert (own chunks), sync
                asm volatile("cp.async.wait_group 0;");
#pragma unroll
                for (int i = 0; i < 8; i++) {
                    int idx = i * 256 + t;
                    int dh = idx >> 5, p4 = idx & 31;
                    float4 v = *(const float4*)(stage + idx * 4);
                    float4 tf;
                    tf.x = __uint_as_float(f2tf32(v.x));
                    tf.y = __uint_as_float(f2tf32(v.y));
                    tf.z = __uint_as_float(f2tf32(v.z));
                    tf.w = __uint_as_float(f2tf32(v.w));
                    *(float4*)(sb + (64 + dh) * 136 + p4 * 4) = tf;
                }
                __syncthreads();
            }
#pragma unroll 4
            for (int ki = 0; ki < 8; ki++) {
                int ks = kg * 8 + ki;
                float4 ah = __ldg(pA + ks * 32 + lane);
                const float* bbase = sb + (ks * 8 + (lane & 3)) * 136 + (lane >> 2);
#pragma unroll
                for (int j = 0; j < 16; j++) {
                    float2 b = make_float2(bbase[j * 8], bbase[544 + j * 8]);
                    mma8(acc[j], ah, b);
                }
            }
        }

        // ---- top-2 over this warp's 16 codes, per pixel ----
        int r0 = half_ * 128 + wid * 16 + (lane >> 2);
#pragma unroll
        for (int j = 0; j < 16; j++) {
#pragma unroll
            for (int cc = 0; cc < 2; cc++) {
                unsigned u0 = mono(acc[j][cc]);       // code r0
                unsigned u1 = mono(acc[j][2 + cc]);   // code r0+8
                ULL k0 = ((ULL)u0 << 32) | (unsigned)(255 - r0);
                ULL k1 = ((ULL)u1 << 32) | (unsigned)(255 - (r0 + 8));
                ULL key = (k0 > k1) ? k0 : k1;
                unsigned us = (u0 < u1) ? u0 : u1;
#pragma unroll
                for (int o = 4; o <= 16; o <<= 1) {
                    ULL ok = __shfl_xor_sync(0xffffffffu, key, o);
                    unsigned os = __shfl_xor_sync(0xffffffffu, us, o);
                    unsigned loser_b = (unsigned)(((key < ok) ? key : ok) >> 32);
                    unsigned win_s = (key > ok) ? us : os;
                    us = (loser_b > win_s) ? loser_b : win_s;
                    key = (key > ok) ? key : ok;
                }
                if (lane < 4) {
                    int px = j * 8 + lane * 2 + cc;
                    gkeys[(half_ * 8 + wid) * 128 + px] = key;
                    gsecs[(half_ * 8 + wid) * 128 + px] = us;
                }
            }
        }
    }
    __syncthreads();

    if (t < 128) {
        int px = t;
        ULL k1 = gkeys[px];
        int g1 = 0;
        unsigned u2 = 0;
#pragma unroll
        for (int g = 1; g < 16; g++) {
            ULL kb = gkeys[g * 128 + px];
            if (kb > k1) {
                unsigned pb = (unsigned)(k1 >> 32);
                if (pb > u2) u2 = pb;
                k1 = kb; g1 = g;
            } else {
                unsigned pb = (unsigned)(kb >> 32);
                if (pb > u2) u2 = pb;
            }
        }
        unsigned sw = gsecs[g1 * 128 + px];
        if (sw > u2) u2 = sw;
        float f1 = imono((unsigned)(k1 >> 32));
        float f2 = imono(u2);
        int code = 255 - (int)(k1 & 0xFF);
        int pix = n * 4096 + p0 + px;
        out[pix * 4 + m] = (float)code;
        if (f1 - f2 < GAP_TH) {
            int pos = atomicAdd(&g_cnt[m], 1);
            g_list[m * 65536 + pos] = pix;
        }
    }
}

// ---------------- stage 2: batched exact fp32 refine (flattened) ------------
// Flat batch index across all m lists; grid 512 so all batches run in one wave.
__global__ __launch_bounds__(256, 2)
void refine_kernel(const float* __restrict__ latent, float* __restrict__ out) {
    __shared__ float xs[128 * 32];     // [d][e]
    __shared__ ULL redk[32 * 64];      // [e][c4]
    __shared__ int spix[32];

    const int t = threadIdx.x;
    const int c0 = g_cnt[0], c1 = g_cnt[1], c2 = g_cnt[2], c3 = g_cnt[3];
    const int nb0 = (c0 + 31) >> 5, nb1 = (c1 + 31) >> 5;
    const int nb2 = (c2 + 31) >> 5, nb3 = (c3 + 31) >> 5;
    const int tot = nb0 + nb1 + nb2 + nb3;

    for (int jb = blockIdx.x; jb < tot; jb += gridDim.x) {
        int m, lb, cnt;
        if (jb < nb0)                  { m = 0; lb = jb; cnt = c0; }
        else if (jb < nb0 + nb1)       { m = 1; lb = jb - nb0; cnt = c1; }
        else if (jb < nb0 + nb1 + nb2) { m = 2; lb = jb - nb0 - nb1; cnt = c2; }
        else                           { m = 3; lb = jb - nb0 - nb1 - nb2; cnt = c3; }
        int ne = cnt - lb * 32;
        if (ne > 32) ne = 32;

        if (t < 32)
            spix[t] = g_list[m * 65536 + lb * 32 + ((t < ne) ? t : 0)];
        __syncthreads();

        // load x for 32 entries: xs[d][e]
        {
            int e = t & 31, d0 = (t >> 5) * 16;
            int pp = spix[e];
            const float* xp = latent +
                ((size_t)((pp >> 12) * 512 + m * 128 + d0)) * 4096 + (pp & 4095);
#pragma unroll 4
            for (int i = 0; i < 16; i++)
                xs[(d0 + i) * 32 + e] = __ldg(xp + (size_t)i * 4096);
        }
        __syncthreads();

        // compute: c4 = t&63 (codes 4c4..+3), eg = t>>6 (8 entries each)
        const int c4 = t & 63, eg = t >> 6;
        float acc[4][8];
#pragma unroll
        for (int c = 0; c < 4; c++)
#pragma unroll
            for (int k = 0; k < 8; k++) acc[c][k] = 0.f;

        const float4* MT = (const float4*)(g_MT + (size_t)m * 32768);
#pragma unroll 4
        for (int d = 0; d < 128; d++) {
            float4 mv = __ldg(MT + d * 64 + c4);
            float4 xa = *(const float4*)(xs + d * 32 + eg * 8);
            float4 xc = *(const float4*)(xs + d * 32 + eg * 8 + 4);
            float xv[8] = {xa.x, xa.y, xa.z, xa.w, xc.x, xc.y, xc.z, xc.w};
#pragma unroll
            for (int k = 0; k < 8; k++) {
                acc[0][k] += mv.x * xv[k];
                acc[1][k] += mv.y * xv[k];
                acc[2][k] += mv.z * xv[k];
                acc[3][k] += mv.w * xv[k];
            }
        }

#pragma unroll
        for (int k = 0; k < 8; k++) {
            ULL key = 0;
#pragma unroll
            for (int c = 0; c < 4; c++) {
                int code = c4 * 4 + c;
                ULL kk = ((ULL)mono(acc[c][k]) << 32) | (unsigned)(255 - code);
                if (kk > key) key = kk;
            }
            redk[(eg * 8 + k) * 64 + c4] = key;
        }
        __syncthreads();

        {
            int e2 = t >> 3, ch = t & 7;
            ULL best = redk[e2 * 64 + ch * 8];
#pragma unroll
            for (int q = 1; q < 8; q++) {
                ULL o = redk[e2 * 64 + ch * 8 + q];
                if (o > best) best = o;
            }
#pragma unroll
            for (int o = 1; o < 8; o <<= 1) {
                ULL ob = __shfl_xor_sync(0xffffffffu, best, o);
                if (ob > best) best = ob;
            }
            if (ch == 0 && e2 < ne)
                out[spix[e2] * 4 + m] = (float)(255 - (int)(best & 0xFF));
        }
        __syncthreads();
    }
}

extern "C" void kernel_launch(void* const* d_in, const int* in_sizes, int n_in,
                              void* d_out, int out_size) {
    const float* latent = (const float*)d_in[0];
    const float* cb     = (const float*)d_in[1];
    const float* wq     = (const float*)d_in[2];
    const float* wk     = (const float*)d_in[3];

    cudaFuncSetAttribute(setup_kernel, cudaFuncAttributeMaxDynamicSharedMemorySize, 74240);
    cudaFuncSetAttribute(score_kernel, cudaFuncAttributeMaxDynamicSharedMemorySize, 102400);

    setup_kernel<<<dim3(32, 4), 256, 74240>>>(cb, wk, wq);
    score_kernel<<<dim3(512, 4), 256, 102400>>>(latent, (float*)d_out);
    refine_kernel<<<512, 256>>>(latent, (float*)d_out);
}

// round 9
// speedup vs baseline: 3.6176x; 1.0026x over previous
#include <cuda_runtime.h>
#include <cstdint>

// ---------------------------------------------------------------------------
// QuantizerEncoder: 1-pass tf32 HMMA + top-2 gap; flagged entries compacted
// and exactly recomputed in fp32 (batched, coalesced).
//
//   score[code][px] = sum_d Mmat[code][d] * x[d][px]
//   out[n,h,w,m] = argmax_code score  (float-coded index)
// ---------------------------------------------------------------------------

typedef unsigned long long ULL;

__device__ float g_A[262144];             // tf32-hi, m16n8k8 A-frag layout
__device__ float g_MT[4 * 128 * 256];     // fp32 M^T [m][d][k] (refine)
__device__ int   g_cnt[4];                // flagged counts per m
__device__ int   g_list[4 * 65536];       // flagged pixel lists per m

#define GAP_TH 0.05f

static __device__ __forceinline__ uint32_t f2tf32(float v) {
    uint32_t u;
    asm("cvt.rna.tf32.f32 %0, %1;" : "=r"(u) : "f"(v));
    return u;
}

static __device__ __forceinline__ uint32_t smem_u32(const void* p) {
    uint32_t a;
    asm("{ .reg .u64 t; cvta.to.shared.u64 t, %1; cvt.u32.u64 %0, t; }"
        : "=r"(a) : "l"(p));
    return a;
}

static __device__ __forceinline__ void mma8(float* d, float4 a, float2 b) {
    asm volatile(
        "mma.sync.aligned.m16n8k8.row.col.f32.tf32.tf32.f32 "
        "{%0,%1,%2,%3}, {%4,%5,%6,%7}, {%8,%9}, {%0,%1,%2,%3};"
        : "+f"(d[0]), "+f"(d[1]), "+f"(d[2]), "+f"(d[3])
        : "r"(__float_as_uint(a.x)), "r"(__float_as_uint(a.y)),
          "r"(__float_as_uint(a.z)), "r"(__float_as_uint(a.w)),
          "r"(__float_as_uint(b.x)), "r"(__float_as_uint(b.y)));
}

static __device__ __forceinline__ unsigned mono(float f) {
    unsigned u = __float_as_uint(f);
    return (u & 0x80000000u) ? ~u : (u | 0x80000000u);
}
static __device__ __forceinline__ float imono(unsigned u) {
    return (u & 0x80000000u) ? __uint_as_float(u & 0x7fffffffu)
                             : __uint_as_float(~u);
}

// ---------------- fused setup: keys (smem) -> Mmat -> g_A/g_MT --------------
// grid (32, 4), 256 threads. smem: region0 16512 f (swkT [128][129] then
// swq [128c][128d]), skeys @16512 (1024 f), scb @17536 (1024 f). 74240 B.
__global__ __launch_bounds__(256, 1)
void setup_kernel(const float* __restrict__ cb, const float* __restrict__ wk,
                  const float* __restrict__ wq) {
    extern __shared__ float sm[];
    float* skeys = sm + 16512;   // [8 k][128 c]
    float* scb   = sm + 17536;   // [8 k][128 d]
    const int m = blockIdx.y, kch = blockIdx.x, t = threadIdx.x;

    // phase 1: keys[k][c] = sum_d cb[k][d] * wk[c][d]
    const float4* wk4 = (const float4*)(wk + (size_t)m * 16384);
#pragma unroll
    for (int i = 0; i < 16; i++) {
        int j = i * 256 + t, c = j >> 5, d4 = j & 31;
        float4 v = __ldg(wk4 + j);
        sm[(4 * d4 + 0) * 129 + c] = v.x;
        sm[(4 * d4 + 1) * 129 + c] = v.y;
        sm[(4 * d4 + 2) * 129 + c] = v.z;
        sm[(4 * d4 + 3) * 129 + c] = v.w;
    }
    ((float4*)scb)[t] = __ldg((const float4*)(cb + ((size_t)m * 256 + kch * 8) * 128) + t);
    __syncthreads();
    {
        // register-blocked: thread computes kl = b, b+2, b+4, b+6 for one c
        int c = t & 127, b = t >> 7;
        float s0 = 0.f, s1 = 0.f, s2 = 0.f, s3 = 0.f;
#pragma unroll 8
        for (int d = 0; d < 128; d++) {
            float w = sm[d * 129 + c];
            s0 += scb[(b + 0) * 128 + d] * w;   // warp-uniform scb -> broadcast
            s1 += scb[(b + 2) * 128 + d] * w;
            s2 += scb[(b + 4) * 128 + d] * w;
            s3 += scb[(b + 6) * 128 + d] * w;
        }
        skeys[(b + 0) * 128 + c] = s0;
        skeys[(b + 2) * 128 + c] = s1;
        skeys[(b + 4) * 128 + c] = s2;
        skeys[(b + 6) * 128 + c] = s3;
    }
    __syncthreads();

    // phase 2: Mmat[k][d] = sum_c wq[c][d] * keys[k][c]
    const float4* wq4 = (const float4*)(wq + (size_t)m * 16384);
#pragma unroll
    for (int i = 0; i < 16; i++) ((float4*)sm)[i * 256 + t] = __ldg(wq4 + i * 256 + t);
    __syncthreads();
    {
        int d = t & 127, b = t >> 7;
        float v0 = 0.f, v1 = 0.f, v2 = 0.f, v3 = 0.f;
#pragma unroll 8
        for (int c = 0; c < 128; c++) {
            float w = sm[c * 128 + d];
            v0 += w * skeys[(b + 0) * 128 + c];
            v1 += w * skeys[(b + 2) * 128 + c];
            v2 += w * skeys[(b + 4) * 128 + c];
            v3 += w * skeys[(b + 6) * 128 + c];
        }
        float vals[4] = {v0, v1, v2, v3};
#pragma unroll
        for (int q = 0; q < 4; q++) {
            int kl = b + 2 * q;
            int k = kch * 8 + kl;
            float val = vals[q];
            g_MT[((size_t)m * 128 + d) * 256 + k] = val;

            uint32_t hib = f2tf32(val);
            int half_ = k >> 7, w = (k & 127) >> 4, r = k & 15;
            int ks = d >> 3, dc = d & 7;
            int ln, fi;
            if (r < 8) { ln = r * 4 + (dc & 3); fi = (dc >= 4) ? 2 : 0; }
            else       { ln = (r - 8) * 4 + (dc & 3); fi = (dc >= 4) ? 3 : 1; }
            size_t base = (size_t)(((m * 2 + half_) * 8 + w) * 16 + ks) * 128 + ln * 4 + fi;
            g_A[base] = __uint_as_float(hib);
        }
    }
    if (blockIdx.x == 0 && blockIdx.y == 0 && t < 4) g_cnt[t] = 0;
}

// ---------------- stage 1: 1-pass tf32 + top-2 + flag compaction ------------
// CTA: 256 threads, 128 px, one m. grid = (512, 4). 2 CTAs/SM.
// smem floats: [0,17408) B tf32 [128 d][136]; [17408,25600) staging raw hi-d;
// gkeys ULL[16][128] @17408 and gsecs u32 @21504 overlap staging (staging is
// dead before they are written). Total 102400 B.
__global__ __launch_bounds__(256, 2)
void score_kernel(const float* __restrict__ latent, float* __restrict__ out) {
    extern __shared__ float sb[];
    float* stage = sb + 17408;
    ULL* gkeys = (ULL*)(sb + 17408);
    unsigned* gsecs = (unsigned*)(sb + 21504);

    const int t = threadIdx.x, lane = t & 31, wid = t >> 5;
    const int m = blockIdx.y;
    const int n = blockIdx.x >> 5;
    const int p0 = (blockIdx.x & 31) << 7;

    const float* xb = latent + ((size_t)(n * 512 + m * 128)) * 4096 + p0;
    const uint32_t stg = smem_u32(stage);

    // kick off async stage of hi-d half (d 64..127) raw fp32
#pragma unroll
    for (int i = 0; i < 8; i++) {
        int idx = i * 256 + t;
        int dh = idx >> 5, p4 = idx & 31;
        const float* src = xb + (size_t)(64 + dh) * 4096 + p4 * 4;
        asm volatile("cp.async.cg.shared.global [%0], [%1], 16;"
                     :: "r"(stg + idx * 16), "l"(src));
    }
    asm volatile("cp.async.commit_group;");

    // direct conversion of lo-d half (d 0..63)
#pragma unroll
    for (int i = 0; i < 8; i++) {
        int idx = i * 256 + t;
        int d = idx >> 5, p4 = idx & 31;
        float4 v = __ldg((const float4*)(xb + (size_t)d * 4096) + p4);
        float4 tf;
        tf.x = __uint_as_float(f2tf32(v.x));
        tf.y = __uint_as_float(f2tf32(v.y));
        tf.z = __uint_as_float(f2tf32(v.z));
        tf.w = __uint_as_float(f2tf32(v.w));
        *(float4*)(sb + d * 136 + p4 * 4) = tf;
    }
    __syncthreads();

    for (int half_ = 0; half_ < 2; half_++) {
        float acc[16][4];
#pragma unroll
        for (int j = 0; j < 16; j++)
#pragma unroll
            for (int c = 0; c < 4; c++) acc[j][c] = 0.f;

        const float4* pA = ((const float4*)g_A) +
                           (size_t)((m * 2 + half_) * 8 + wid) * 512;

        for (int kg = 0; kg < 2; kg++) {
            // preload this kg's 8 A-frags into registers (LDGs fly during the
            // hi-half conversion below on the half0/kg1 iteration)
            float4 afr[8];
#pragma unroll
            for (int ki = 0; ki < 8; ki++)
                afr[ki] = __ldg(pA + (kg * 8 + ki) * 32 + lane);

            if (half_ == 0 && kg == 1) {
                asm volatile("cp.async.wait_group 0;");
#pragma unroll
                for (int i = 0; i < 8; i++) {
                    int idx = i * 256 + t;
                    int dh = idx >> 5, p4 = idx & 31;
                    float4 v = *(const float4*)(stage + idx * 4);
                    float4 tf;
                    tf.x = __uint_as_float(f2tf32(v.x));
                    tf.y = __uint_as_float(f2tf32(v.y));
                    tf.z = __uint_as_float(f2tf32(v.z));
                    tf.w = __uint_as_float(f2tf32(v.w));
                    *(float4*)(sb + (64 + dh) * 136 + p4 * 4) = tf;
                }
                __syncthreads();
            }
#pragma unroll
            for (int ki = 0; ki < 8; ki++) {
                int ks = kg * 8 + ki;
                const float* bbase = sb + (ks * 8 + (lane & 3)) * 136 + (lane >> 2);
#pragma unroll
                for (int j = 0; j < 16; j++) {
                    float2 b = make_float2(bbase[j * 8], bbase[544 + j * 8]);
                    mma8(acc[j], afr[ki], b);
                }
            }
        }

        // ---- top-2 over this warp's 16 codes, per pixel ----
        int r0 = half_ * 128 + wid * 16 + (lane >> 2);
#pragma unroll
        for (int j = 0; j < 16; j++) {
#pragma unroll
            for (int cc = 0; cc < 2; cc++) {
                unsigned u0 = mono(acc[j][cc]);       // code r0
                unsigned u1 = mono(acc[j][2 + cc]);   // code r0+8
                ULL k0 = ((ULL)u0 << 32) | (unsigned)(255 - r0);
                ULL k1 = ((ULL)u1 << 32) | (unsigned)(255 - (r0 + 8));
                ULL key = (k0 > k1) ? k0 : k1;
                unsigned us = (u0 < u1) ? u0 : u1;
#pragma unroll
                for (int o = 4; o <= 16; o <<= 1) {
                    ULL ok = __shfl_xor_sync(0xffffffffu, key, o);
                    unsigned os = __shfl_xor_sync(0xffffffffu, us, o);
                    unsigned loser_b = (unsigned)(((key < ok) ? key : ok) >> 32);
                    unsigned win_s = (key > ok) ? us : os;
                    us = (loser_b > win_s) ? loser_b : win_s;
                    key = (key > ok) ? key : ok;
                }
                if (lane < 4) {
                    int px = j * 8 + lane * 2 + cc;
                    gkeys[(half_ * 8 + wid) * 128 + px] = key;
                    gsecs[(half_ * 8 + wid) * 128 + px] = us;
                }
            }
        }
    }
    __syncthreads();

    if (t < 128) {
        int px = t;
        ULL k1 = gkeys[px];
        int g1 = 0;
        unsigned u2 = 0;
#pragma unroll
        for (int g = 1; g < 16; g++) {
            ULL kb = gkeys[g * 128 + px];
            if (kb > k1) {
                unsigned pb = (unsigned)(k1 >> 32);
                if (pb > u2) u2 = pb;
                k1 = kb; g1 = g;
            } else {
                unsigned pb = (unsigned)(kb >> 32);
                if (pb > u2) u2 = pb;
            }
        }
        unsigned sw = gsecs[g1 * 128 + px];
        if (sw > u2) u2 = sw;
        float f1 = imono((unsigned)(k1 >> 32));
        float f2 = imono(u2);
        int code = 255 - (int)(k1 & 0xFF);
        int pix = n * 4096 + p0 + px;
        out[pix * 4 + m] = (float)code;
        if (f1 - f2 < GAP_TH) {
            int pos = atomicAdd(&g_cnt[m], 1);
            g_list[m * 65536 + pos] = pix;
        }
    }
}

// ---------------- stage 2: batched exact fp32 refine (flattened) ------------
__global__ __launch_bounds__(256, 2)
void refine_kernel(const float* __restrict__ latent, float* __restrict__ out) {
    __shared__ float xs[128 * 32];     // [d][e]
    __shared__ ULL redk[32 * 64];      // [e][c4]
    __shared__ int spix[32];

    const int t = threadIdx.x;
    const int c0 = g_cnt[0], c1 = g_cnt[1], c2 = g_cnt[2], c3 = g_cnt[3];
    const int nb0 = (c0 + 31) >> 5, nb1 = (c1 + 31) >> 5;
    const int nb2 = (c2 + 31) >> 5, nb3 = (c3 + 31) >> 5;
    const int tot = nb0 + nb1 + nb2 + nb3;

    for (int jb = blockIdx.x; jb < tot; jb += gridDim.x) {
        int m, lb, cnt;
        if (jb < nb0)                  { m = 0; lb = jb; cnt = c0; }
        else if (jb < nb0 + nb1)       { m = 1; lb = jb - nb0; cnt = c1; }
        else if (jb < nb0 + nb1 + nb2) { m = 2; lb = jb - nb0 - nb1; cnt = c2; }
        else                           { m = 3; lb = jb - nb0 - nb1 - nb2; cnt = c3; }
        int ne = cnt - lb * 32;
        if (ne > 32) ne = 32;

        if (t < 32)
            spix[t] = g_list[m * 65536 + lb * 32 + ((t < ne) ? t : 0)];
        __syncthreads();

        // load x for 32 entries: xs[d][e] (full unroll -> MLP 16)
        {
            int e = t & 31, d0 = (t >> 5) * 16;
            int pp = spix[e];
            const float* xp = latent +
                ((size_t)((pp >> 12) * 512 + m * 128 + d0)) * 4096 + (pp & 4095);
            float v[16];
#pragma unroll
            for (int i = 0; i < 16; i++) v[i] = __ldg(xp + (size_t)i * 4096);
#pragma unroll
            for (int i = 0; i < 16; i++) xs[(d0 + i) * 32 + e] = v[i];
        }
        __syncthreads();

        const int c4 = t & 63, eg = t >> 6;
        float acc[4][8];
#pragma unroll
        for (int c = 0; c < 4; c++)
#pragma unroll
            for (int k = 0; k < 8; k++) acc[c][k] = 0.f;

        const float4* MT = (const float4*)(g_MT + (size_t)m * 32768);
#pragma unroll 4
        for (int d = 0; d < 128; d++) {
            float4 mv = __ldg(MT + d * 64 + c4);
            float4 xa = *(const float4*)(xs + d * 32 + eg * 8);
            float4 xc = *(const float4*)(xs + d * 32 + eg * 8 + 4);
            float xv[8] = {xa.x, xa.y, xa.z, xa.w, xc.x, xc.y, xc.z, xc.w};
#pragma unroll
            for (int k = 0; k < 8; k++) {
                acc[0][k] += mv.x * xv[k];
                acc[1][k] += mv.y * xv[k];
                acc[2][k] += mv.z * xv[k];
                acc[3][k] += mv.w * xv[k];
            }
        }

#pragma unroll
        for (int k = 0; k < 8; k++) {
            ULL key = 0;
#pragma unroll
            for (int c = 0; c < 4; c++) {
                int code = c4 * 4 + c;
                ULL kk = ((ULL)mono(acc[c][k]) << 32) | (unsigned)(255 - code);
                if (kk > key) key = kk;
            }
            redk[(eg * 8 + k) * 64 + c4] = key;
        }
        __syncthreads();

        {
            int e2 = t >> 3, ch = t & 7;
            ULL best = redk[e2 * 64 + ch * 8];
#pragma unroll
            for (int q = 1; q < 8; q++) {
                ULL o = redk[e2 * 64 + ch * 8 + q];
                if (o > best) best = o;
            }
#pragma unroll
            for (int o = 1; o < 8; o <<= 1) {
                ULL ob = __shfl_xor_sync(0xffffffffu, best, o);
                if (ob > best) best = ob;
            }
            if (ch == 0 && e2 < ne)
                out[spix[e2] * 4 + m] = (float)(255 - (int)(best & 0xFF));
        }
        __syncthreads();
    }
}

extern "C" void kernel_launch(void* const* d_in, const int* in_sizes, int n_in,
                              void* d_out, int out_size) {
    const float* latent = (const float*)d_in[0];
    const float* cb     = (const float*)d_in[1];
    const float* wq     = (const float*)d_in[2];
    const float* wk     = (const float*)d_in[3];

    cudaFuncSetAttribute(setup_kernel, cudaFuncAttributeMaxDynamicSharedMemorySize, 74240);
    cudaFuncSetAttribute(score_kernel, cudaFuncAttributeMaxDynamicSharedMemorySize, 102400);

    setup_kernel<<<dim3(32, 4), 256, 74240>>>(cb, wk, wq);
    score_kernel<<<dim3(512, 4), 256, 102400>>>(latent, (float*)d_out);
    refine_kernel<<<512, 256>>>(latent, (float*)d_out);
}